// round 3
// baseline (speedup 1.0000x reference)
#include <cuda_runtime.h>
#include <cuda_bf16.h>

// Problem constants (fixed by the dataset shapes)
#define BB   16
#define KK   64
#define HH   160
#define WW   160
#define HWC  (HH * WW)          // 25600
#define NGRP 4                  // k-groups per block
#define KPT  (KK / NGRP)        // 16 keypoints per thread
#define NTHR (WW * NGRP)        // 640 threads
#define EPS_F 1e-5f

__device__ __forceinline__ float ex2_approx(float x) {
    float r;
    asm("ex2.approx.ftz.f32 %0, %1;" : "=f"(r) : "f"(x));
    return r;
}

__global__ __launch_bounds__(NTHR, 2)
void recon_conf_map_kernel(const float* __restrict__ kp,    // [B,K,2] (x,y)
                           const float* __restrict__ psx,   // scalar
                           const float* __restrict__ psy,   // scalar
                           const float* __restrict__ prho,  // scalar
                           float* __restrict__ out)         // [B,K,H,W]
{
    // Per-(k,row) quadratic: e(fx) = Bq*fx^2 + q.y*fx + q.x  (den folded into q.x)
    __shared__ float2 sq[KK];
    __shared__ float  psum[NGRP][WW];

    const int b = blockIdx.x / HH;
    const int y = blockIdx.x % HH;
    const int x = threadIdx.x;        // 0..159
    const int g = threadIdx.y;        // 0..3
    const int tid = g * WW + x;

    // Scalars (broadcast LDG, L1-cached)
    const float sx  = psx[0];
    const float sy  = psy[0];
    const float rho = prho[0];

    const float omr2 = 1.0f - rho * rho;
    const float num1 = -0.5f / omr2;
    const float L2E  = 1.4426950408889634f;           // log2(e)
    const float den  = 1.0f / (6.2831853071795864f * sx * sy * sqrtf(omr2));
    const float l2den = log2f(den);

    // base-2 exponent = A*dy^2 + Bq*dx^2 + C*dy*dx (+ l2den)
    const float A  = num1 * L2E / (sy * sy);
    const float Bq = num1 * L2E / (sx * sx);
    const float C  = num1 * L2E * (-2.0f * rho) / (sx * sy);

    // Per-k 1-D quadratic in fx for this row:
    //   e = Bq*fx^2 + (C*dy - 2*Bq*kx)*fx + [A*dy^2 + Bq*kx^2 - (C*dy)*kx + l2den]
    if (tid < KK) {
        float2 p = reinterpret_cast<const float2*>(kp)[b * KK + tid];
        const float kx = p.x;
        const float dy = (float)y - p.y;
        const float cy = C * dy;
        const float ay = fmaf(A * dy, dy, l2den);
        const float q1 = fmaf(-2.0f * Bq, kx, cy);
        const float q0 = fmaf(kx, fmaf(Bq, kx, -cy), ay);
        sq[tid] = make_float2(q0, q1);
    }
    __syncthreads();

    const float fx   = (float)x;
    const float bfx2 = Bq * fx * fx;
    const int   kbase = g * KPT;

    float vals[KPT];
    float sum0 = 0.0f, sum1 = 0.0f;

#pragma unroll
    for (int k = 0; k < KPT; k += 2) {
        const float2 qa = sq[kbase + k];
        const float2 qb = sq[kbase + k + 1];
        const float ea = fmaf(qa.y, fx, qa.x) + bfx2;
        const float eb = fmaf(qb.y, fx, qb.x) + bfx2;
        const float va = ex2_approx(ea);
        const float vb = ex2_approx(eb);
        vals[k]     = va;
        vals[k + 1] = vb;
        sum0 += va;
        sum1 += vb;
    }

    psum[g][x] = sum0 + sum1;
    __syncthreads();

    const float total = (psum[0][x] + psum[1][x]) + (psum[2][x] + psum[3][x]);
    const float inv   = __fdividef(1.0f, total + EPS_F);

    // out[b, kbase+k, y, x]; each k-store is a coalesced 128B-aligned warp segment
    float* __restrict__ o = out + ((size_t)b * KK + kbase) * HWC + (size_t)y * WW + x;
#pragma unroll
    for (int k = 0; k < KPT; ++k) {
        o[(size_t)k * HWC] = vals[k] * inv;
    }
}

extern "C" void kernel_launch(void* const* d_in, const int* in_sizes, int n_in,
                              void* d_out, int out_size) {
    // metadata order: keypoints, std_x, std_y, correlation, DetectionMap (unused)
    const float* kp   = (const float*)d_in[0];
    const float* psx  = (const float*)d_in[1];
    const float* psy  = (const float*)d_in[2];
    const float* prho = (const float*)d_in[3];
    float* out = (float*)d_out;

    dim3 block(WW, NGRP);                 // 640 threads
    const int grid = BB * HH;             // 2560 blocks, one per (batch,row)
    recon_conf_map_kernel<<<grid, block>>>(kp, psx, psy, prho, out);
}

// round 4
// speedup vs baseline: 1.1748x; 1.1748x over previous
#include <cuda_runtime.h>
#include <cuda_bf16.h>

// Problem constants (fixed by the dataset shapes)
#define BB   16
#define KK   64
#define HH   160
#define WW   160
#define HWC  (HH * WW)          // 25600
#define NQ   (WW / 4)           // 40 x-quads per row
#define NGRP 8                  // k-groups per block
#define KPT  (KK / NGRP)        // 8 keypoints per thread
#define NTHR (NQ * NGRP)        // 320 threads
#define EPS_F 1e-5f

__device__ __forceinline__ float ex2_approx(float x) {
    float r;
    asm("ex2.approx.ftz.f32 %0, %1;" : "=f"(r) : "f"(x));
    return r;
}

__global__ __launch_bounds__(NTHR, 3)
void recon_conf_map_kernel(const float* __restrict__ kp,    // [B,K,2] (x,y)
                           const float* __restrict__ psx,   // scalar
                           const float* __restrict__ psy,   // scalar
                           const float* __restrict__ prho,  // scalar
                           float* __restrict__ out)         // [B,K,H,W]
{
    // Per-(k,row) quadratic: e(fx) = Bq*fx^2 + q.y*fx + q.x  (den folded into q.x)
    __shared__ float2 sq[KK];
    __shared__ float4 psum[NGRP][NQ];

    const int b  = blockIdx.x / HH;
    const int y  = blockIdx.x % HH;
    const int qx = threadIdx.x;          // 0..39  (x-quad)
    const int g  = threadIdx.y;          // 0..7   (k-group)
    const int tid = g * NQ + qx;

    // Scalars (broadcast LDG, L1-cached)
    const float sx  = psx[0];
    const float sy  = psy[0];
    const float rho = prho[0];

    const float omr2 = 1.0f - rho * rho;
    const float num1 = -0.5f / omr2;
    const float L2E  = 1.4426950408889634f;           // log2(e)
    const float den  = 1.0f / (6.2831853071795864f * sx * sy * sqrtf(omr2));
    const float l2den = log2f(den);

    // base-2 exponent = A*dy^2 + Bq*dx^2 + C*dy*dx (+ l2den)
    const float A  = num1 * L2E / (sy * sy);
    const float Bq = num1 * L2E / (sx * sx);
    const float C  = num1 * L2E * (-2.0f * rho) / (sx * sy);

    // Per-k 1-D quadratic in fx for this row:
    //   e = Bq*fx^2 + (C*dy - 2*Bq*kx)*fx + [A*dy^2 + Bq*kx^2 - (C*dy)*kx + l2den]
    if (tid < KK) {
        float2 p = reinterpret_cast<const float2*>(kp)[b * KK + tid];
        const float kx = p.x;
        const float dy = (float)y - p.y;
        const float cy = C * dy;
        const float ay = fmaf(A * dy, dy, l2den);
        const float q1 = fmaf(-2.0f * Bq, kx, cy);
        const float q0 = fmaf(kx, fmaf(Bq, kx, -cy), ay);
        sq[tid] = make_float2(q0, q1);
    }
    __syncthreads();

    const float fx0 = (float)(4 * qx);
    const float4 fxv = make_float4(fx0, fx0 + 1.0f, fx0 + 2.0f, fx0 + 3.0f);
    // bfx2 per lane-x, with nothing foldable per-k
    const float4 bf = make_float4(Bq * fxv.x * fxv.x, Bq * fxv.y * fxv.y,
                                  Bq * fxv.z * fxv.z, Bq * fxv.w * fxv.w);
    const int kbase = g * KPT;

    float4 vals[KPT];
    float4 sum = make_float4(0.f, 0.f, 0.f, 0.f);

#pragma unroll
    for (int k = 0; k < KPT; ++k) {
        const float2 q = sq[kbase + k];
        float4 v;
        v.x = ex2_approx(fmaf(q.y, fxv.x, q.x) + bf.x);
        v.y = ex2_approx(fmaf(q.y, fxv.y, q.x) + bf.y);
        v.z = ex2_approx(fmaf(q.y, fxv.z, q.x) + bf.z);
        v.w = ex2_approx(fmaf(q.y, fxv.w, q.x) + bf.w);
        vals[k] = v;
        sum.x += v.x; sum.y += v.y; sum.z += v.z; sum.w += v.w;
    }

    psum[g][qx] = sum;
    __syncthreads();

    // Total over the 8 k-groups for this x-quad
    float4 t = psum[0][qx];
#pragma unroll
    for (int gg = 1; gg < NGRP; ++gg) {
        const float4 p = psum[gg][qx];
        t.x += p.x; t.y += p.y; t.z += p.z; t.w += p.w;
    }
    const float4 inv = make_float4(__fdividef(1.0f, t.x + EPS_F),
                                   __fdividef(1.0f, t.y + EPS_F),
                                   __fdividef(1.0f, t.z + EPS_F),
                                   __fdividef(1.0f, t.w + EPS_F));

    // out[b, kbase+k, y, 4*qx .. 4*qx+3] — one STG.128 per k, coalesced per warp
    float4* __restrict__ o = reinterpret_cast<float4*>(
        out + ((size_t)b * KK + kbase) * HWC + (size_t)y * WW) + qx;
#pragma unroll
    for (int k = 0; k < KPT; ++k) {
        const float4 v = vals[k];
        o[(size_t)k * (HWC / 4)] = make_float4(v.x * inv.x, v.y * inv.y,
                                               v.z * inv.z, v.w * inv.w);
    }
}

extern "C" void kernel_launch(void* const* d_in, const int* in_sizes, int n_in,
                              void* d_out, int out_size) {
    // metadata order: keypoints, std_x, std_y, correlation, DetectionMap (unused)
    const float* kp   = (const float*)d_in[0];
    const float* psx  = (const float*)d_in[1];
    const float* psy  = (const float*)d_in[2];
    const float* prho = (const float*)d_in[3];
    float* out = (float*)d_out;

    dim3 block(NQ, NGRP);                 // 320 threads
    const int grid = BB * HH;             // 2560 blocks, one per (batch,row)
    recon_conf_map_kernel<<<grid, block>>>(kp, psx, psy, prho, out);
}